// round 16
// baseline (speedup 1.0000x reference)
#include <cuda_runtime.h>
#include <cuda_bf16.h>
#include <math.h>
#include <stdint.h>

// Problem constants
#define Bx   1024
#define Lx   200
#define Dx   128
#define Hx   4
#define DKx  32
#define FFx  512
#define NLx  2
#define NT   (Bx*Lx)          // 204800 tokens
#define FCK  (Lx*Dx)          // 25600
#define FCZ  25               // FC K-split

// ---------------------------------------------------------------------------
// Device-global scratch (allocation-free rule).
// ---------------------------------------------------------------------------
__device__ float g_x  [(size_t)NT * Dx];    // residual stream (fp32)
__device__ float g_q  [(size_t)NT * Dx];
__device__ float g_k  [(size_t)NT * Dx];
__device__ float g_v  [(size_t)NT * Dx];
__device__ float g_fcp[(size_t)32 * Bx * Dx];

// bf16 hi/lo activation planes
__device__ __nv_bfloat16 g_ah[(size_t)NT * Dx],  g_al[(size_t)NT * Dx];
__device__ __nv_bfloat16 g_oh[(size_t)NT * Dx],  g_ol[(size_t)NT * Dx];
__device__ __nv_bfloat16 g_fh[(size_t)NT * FFx], g_fl[(size_t)NT * FFx];

// transposed+split weights [N][K]
#define LW 196608
__device__ __nv_bfloat16 g_wh[(size_t)NLx * LW], g_wl[(size_t)NLx * LW];
__device__ __nv_bfloat16 g_fcwh[(size_t)Dx * FCK], g_fcwl[(size_t)Dx * FCK];

// ---------------------------------------------------------------------------
// Helpers
// ---------------------------------------------------------------------------
__device__ __forceinline__ uint32_t smem_u32(const void* p) {
    uint32_t a;
    asm("{ .reg .u64 t; cvta.to.shared.u64 t, %1; cvt.u32.u64 %0, t; }" : "=r"(a) : "l"(p));
    return a;
}
__device__ __forceinline__ void ldm4(uint32_t* r, uint32_t addr) {
    asm volatile("ldmatrix.sync.aligned.m8n8.x4.shared.b16 {%0,%1,%2,%3}, [%4];"
                 : "=r"(r[0]), "=r"(r[1]), "=r"(r[2]), "=r"(r[3]) : "r"(addr));
}
__device__ __forceinline__ void mma_bf16(float* d, const uint32_t* a, const uint32_t* b) {
    asm volatile("mma.sync.aligned.m16n8k16.row.col.f32.bf16.bf16.f32 "
                 "{%0,%1,%2,%3}, {%4,%5,%6,%7}, {%8,%9}, {%0,%1,%2,%3};"
                 : "+f"(d[0]), "+f"(d[1]), "+f"(d[2]), "+f"(d[3])
                 : "r"(a[0]), "r"(a[1]), "r"(a[2]), "r"(a[3]), "r"(b[0]), "r"(b[1]));
}
#define CP_COMMIT() asm volatile("cp.async.commit_group;" ::: "memory")
#define CP_WAIT0()  asm volatile("cp.async.wait_group 0;" ::: "memory")

__device__ __forceinline__ void split_store(__nv_bfloat16* oh, __nv_bfloat16* ol,
                                            size_t ci, float y0, float y1) {
    __nv_bfloat16 h0 = __float2bfloat16(y0), h1 = __float2bfloat16(y1);
    *(__nv_bfloat162*)(oh + ci) = __halves2bfloat162(h0, h1);
    *(__nv_bfloat162*)(ol + ci) = __halves2bfloat162(
        __float2bfloat16(y0 - __bfloat162float(h0)),
        __float2bfloat16(y1 - __bfloat162float(h1)));
}

// ---------------------------------------------------------------------------
// Weight transpose + bf16 split (single launch, all layer weights)
// ---------------------------------------------------------------------------
__global__ void wconv_all(const float* __restrict__ Wq, const float* __restrict__ Wk,
                          const float* __restrict__ Wv, const float* __restrict__ Wo,
                          const float* __restrict__ W1, const float* __restrict__ W2,
                          __nv_bfloat16* __restrict__ Th, __nv_bfloat16* __restrict__ Tl) {
    int idx = blockIdx.x * 256 + threadIdx.x;
    if (idx >= NLx * LW) return;
    int l = idx / LW, o = idx % LW;
    float v;
    if (o < 65536) {
        int seg = o >> 14, loc = o & 16383;
        int n = loc >> 7, k = loc & 127;
        const float* W = (seg == 0) ? Wq : (seg == 1) ? Wk : (seg == 2) ? Wv : Wo;
        v = W[(size_t)l * Dx * Dx + k * Dx + n];
    } else if (o < 131072) {
        int loc = o - 65536;
        int n = loc >> 7, k = loc & 127;
        v = W1[(size_t)l * Dx * FFx + k * FFx + n];
    } else {
        int loc = o - 131072;
        int n = loc >> 9, k = loc & 511;
        v = W2[(size_t)l * FFx * Dx + k * Dx + n];
    }
    __nv_bfloat16 h = __float2bfloat16(v);
    Th[idx] = h;
    Tl[idx] = __float2bfloat16(v - __bfloat162float(h));
}

__global__ void wconv_fc(const float* __restrict__ W,
                         __nv_bfloat16* __restrict__ Th, __nv_bfloat16* __restrict__ Tl) {
    int idx = blockIdx.x * 256 + threadIdx.x;
    if (idx >= Dx * FCK) return;
    int n = idx / FCK, k = idx % FCK;
    float v = W[(size_t)k * Dx + n];
    __nv_bfloat16 h = __float2bfloat16(v);
    Th[idx] = h;
    Tl[idx] = __float2bfloat16(v - __bfloat162float(h));
}

// ---------------------------------------------------------------------------
// Embedding
// ---------------------------------------------------------------------------
__global__ void embed_k(const int* __restrict__ seqs, const float* __restrict__ tok,
                        const float* __restrict__ pos, float* __restrict__ x) {
    int t = blockIdx.x * 8 + (threadIdx.x >> 5);
    int lane = threadIdx.x & 31;
    if (t >= NT) return;
    int id = seqs[t], l = t % Lx;
    float4 te = *(const float4*)(tok + (size_t)id * Dx + lane * 4);
    float4 pe = *(const float4*)(pos + (size_t)l  * Dx + lane * 4);
    *(float4*)(x + (size_t)t * Dx + lane * 4) =
        make_float4(te.x + pe.x, te.y + pe.y, te.z + pe.z, te.w + pe.w);
}

// ---------------------------------------------------------------------------
// Standalone LayerNorm -> bf16 hi/lo planes (layer 0 ln1 only)
// ---------------------------------------------------------------------------
__global__ void ln_k(const float* __restrict__ x, const float* __restrict__ w,
                     const float* __restrict__ b,
                     __nv_bfloat16* __restrict__ oh, __nv_bfloat16* __restrict__ ol) {
    int r = blockIdx.x * 8 + (threadIdx.x >> 5);
    int lane = threadIdx.x & 31;
    if (r >= NT) return;
    float4 v = *(const float4*)(x + (size_t)r * Dx + lane * 4);
    float s = v.x + v.y + v.z + v.w;
#pragma unroll
    for (int o = 16; o; o >>= 1) s += __shfl_xor_sync(~0u, s, o);
    float mu = s * (1.f / 128.f);
    float dx = v.x - mu, dy = v.y - mu, dz = v.z - mu, dw = v.w - mu;
    float s2 = dx*dx + dy*dy + dz*dz + dw*dw;
#pragma unroll
    for (int o = 16; o; o >>= 1) s2 += __shfl_xor_sync(~0u, s2, o);
    float rs = rsqrtf(s2 * (1.f / 128.f) + 1e-5f);
    float4 wv = *(const float4*)(w + lane * 4);
    float4 bv = *(const float4*)(b + lane * 4);
    size_t o = (size_t)r * Dx + lane * 4;
    split_store(oh, ol, o,     dx*rs*wv.x + bv.x, dy*rs*wv.y + bv.y);
    split_store(oh, ol, o + 2, dz*rs*wv.z + bv.z, dw*rs*wv.w + bv.w);
}

// ---------------------------------------------------------------------------
// GEMM tiles/layout
// ---------------------------------------------------------------------------
#define PAD 136
#define PLANE (128 * PAD * 2)        // 34816 bytes
#define LNRED (128 * 4 * 2 * 4)      // 4096 bytes (rsum+rsq [128][4])
#define TG_SMEM    (6 * PLANE)               // 208896
#define TG_SMEM_LN (6 * PLANE + LNRED)       // 212992
#define PAD2 72
#define HPLANE (128 * PAD2 * 2)      // 18432 bytes
#define W2_SMEM_LN (8 * HPLANE + LNRED)      // 151552
#define FC_SMEM    (8 * HPLANE)              // 147456

__device__ __forceinline__ void stage_async(const __nv_bfloat16* __restrict__ src, int ld,
                                            uint32_t smbase, int tid) {
#pragma unroll
    for (int it = 0; it < 8; ++it) {
        int i = it * 256 + tid;
        int row = i >> 4, seg = (i & 15) << 3;
        uint32_t dst = smbase + (row * PAD + seg) * 2;
        asm volatile("cp.async.cg.shared.global [%0], [%1], 16;"
                     :: "r"(dst), "l"(src + (size_t)row * ld + seg) : "memory");
    }
}
__device__ __forceinline__ void stage_async64(const __nv_bfloat16* __restrict__ src, int ld,
                                              uint32_t smbase, int tid) {
#pragma unroll
    for (int it = 0; it < 4; ++it) {
        int i = it * 256 + tid;
        int row = i >> 3, seg = (i & 7) << 3;
        uint32_t dst = smbase + (row * PAD2 + seg) * 2;
        asm volatile("cp.async.cg.shared.global [%0], [%1], 16;"
                     :: "r"(dst), "l"(src + (size_t)row * ld + seg) : "memory");
    }
}

__device__ __forceinline__ void mma_chunk(
    float acc[4][4][4], uint32_t sAh, uint32_t sAl, uint32_t sBh, uint32_t sBl,
    uint32_t aoff, uint32_t boff)
{
#pragma unroll
    for (int ks = 0; ks < 8; ++ks) {
        uint32_t kb = ks * 32;
        uint32_t fah[4][4], fal[4][4], fbh[4][2], fbl[4][2];
#pragma unroll
        for (int mi = 0; mi < 4; ++mi) {
            uint32_t ro = mi * 16 * PAD * 2 + kb;
            ldm4(fah[mi], sAh + aoff + ro);
            ldm4(fal[mi], sAl + aoff + ro);
        }
#pragma unroll
        for (int np = 0; np < 2; ++np) {
            uint32_t ro = np * 16 * PAD * 2 + kb;
            ldm4(&fbh[2 * np][0], sBh + boff + ro);
            ldm4(&fbl[2 * np][0], sBl + boff + ro);
        }
#pragma unroll
        for (int mi = 0; mi < 4; ++mi)
#pragma unroll
            for (int ni = 0; ni < 4; ++ni) {
                mma_bf16(acc[mi][ni], fah[mi], fbh[ni]);
                mma_bf16(acc[mi][ni], fah[mi], fbl[ni]);
                mma_bf16(acc[mi][ni], fal[mi], fbh[ni]);
            }
    }
}
__device__ __forceinline__ void mma_chunk64(
    float acc[4][4][4], uint32_t sAh, uint32_t sAl, uint32_t sBh, uint32_t sBl,
    uint32_t aoff, uint32_t boff)
{
#pragma unroll
    for (int ks = 0; ks < 4; ++ks) {
        uint32_t kb = ks * 32;
        uint32_t fah[4][4], fal[4][4], fbh[4][2], fbl[4][2];
#pragma unroll
        for (int mi = 0; mi < 4; ++mi) {
            uint32_t ro = mi * 16 * PAD2 * 2 + kb;
            ldm4(fah[mi], sAh + aoff + ro);
            ldm4(fal[mi], sAl + aoff + ro);
        }
#pragma unroll
        for (int np = 0; np < 2; ++np) {
            uint32_t ro = np * 16 * PAD2 * 2 + kb;
            ldm4(&fbh[2 * np][0], sBh + boff + ro);
            ldm4(&fbl[2 * np][0], sBl + boff + ro);
        }
#pragma unroll
        for (int mi = 0; mi < 4; ++mi)
#pragma unroll
            for (int ni = 0; ni < 4; ++ni) {
                mma_bf16(acc[mi][ni], fah[mi], fbh[ni]);
                mma_bf16(acc[mi][ni], fah[mi], fbl[ni]);
                mma_bf16(acc[mi][ni], fal[mi], fbh[ni]);
            }
    }
}

// ---------------------------------------------------------------------------
// Fused epilogue: acc holds post-bias(+res) values; write Cf; then LN (or
// plain split if lnw==nullptr) into oh/ol. rsum/rsq: smem [128][4] each.
// CTA must cover the full 128-wide row (n0==0). acc IS modified.
// ---------------------------------------------------------------------------
__device__ __forceinline__ void epi_ln_split(
    float acc[4][4][4], const float* __restrict__ bias, const float* __restrict__ res,
    float* __restrict__ Cf, const float* __restrict__ lnw, const float* __restrict__ lnb,
    __nv_bfloat16* __restrict__ oh, __nv_bfloat16* __restrict__ ol,
    float* rsum, float* rsq, int m0, int wm, int wn, int lane)
{
    int gp = lane >> 2, t4 = lane & 3;
    float s8[8], q8[8];
#pragma unroll
    for (int mi = 0; mi < 4; ++mi) {
        float s0 = 0.f, q0 = 0.f, s1 = 0.f, q1 = 0.f;
        int r0 = m0 + wm * 64 + mi * 16 + gp;
#pragma unroll
        for (int ni = 0; ni < 4; ++ni) {
            int ncol = wn * 32 + ni * 8 + t4 * 2;
            float b0 = bias[ncol], b1 = bias[ncol + 1];
            size_t ci0 = (size_t)r0 * Dx + ncol, ci1 = ci0 + 8 * Dx;
            float2 rv0 = *(const float2*)(res + ci0);
            float2 rv1 = *(const float2*)(res + ci1);
            float d0 = acc[mi][ni][0] + b0 + rv0.x;
            float d1 = acc[mi][ni][1] + b1 + rv0.y;
            float d2 = acc[mi][ni][2] + b0 + rv1.x;
            float d3 = acc[mi][ni][3] + b1 + rv1.y;
            acc[mi][ni][0] = d0; acc[mi][ni][1] = d1;
            acc[mi][ni][2] = d2; acc[mi][ni][3] = d3;
            *(float2*)(Cf + ci0) = make_float2(d0, d1);
            *(float2*)(Cf + ci1) = make_float2(d2, d3);
            s0 += d0 + d1; q0 += d0 * d0 + d1 * d1;
            s1 += d2 + d3; q1 += d2 * d2 + d3 * d3;
        }
        s8[2*mi] = s0; q8[2*mi] = q0; s8[2*mi+1] = s1; q8[2*mi+1] = q1;
    }
    if (lnw) {
#pragma unroll
        for (int i = 0; i < 8; ++i) {
            s8[i] += __shfl_xor_sync(~0u, s8[i], 1);
            s8[i] += __shfl_xor_sync(~0u, s8[i], 2);
            q8[i] += __shfl_xor_sync(~0u, q8[i], 1);
            q8[i] += __shfl_xor_sync(~0u, q8[i], 2);
        }
        if (t4 == 0) {
#pragma unroll
            for (int mi = 0; mi < 4; ++mi) {
                int lr = wm * 64 + mi * 16 + gp;
                rsum[lr * 4 + wn]       = s8[2*mi];
                rsq [lr * 4 + wn]       = q8[2*mi];
                rsum[(lr + 8) * 4 + wn] = s8[2*mi+1];
                rsq [(lr + 8) * 4 + wn] = q8[2*mi+1];
            }
        }
        __syncthreads();
    }
#pragma unroll
    for (int mi = 0; mi < 4; ++mi) {
        int lr0 = wm * 64 + mi * 16 + gp, lr1 = lr0 + 8;
        float mu0 = 0.f, rs0 = 0.f, mu1 = 0.f, rs1 = 0.f;
        if (lnw) {
            float su0 = rsum[lr0*4] + rsum[lr0*4+1] + rsum[lr0*4+2] + rsum[lr0*4+3];
            float qu0 = rsq [lr0*4] + rsq [lr0*4+1] + rsq [lr0*4+2] + rsq [lr0*4+3];
            float su1 = rsum[lr1*4] + rsum[lr1*4+1] + rsum[lr1*4+2] + rsum[lr1*4+3];
            float qu1 = rsq [lr1*4] + rsq [lr1*4+1] + rsq [lr1*4+2] + rsq [lr1*4+3];
            mu0 = su0 * (1.f/128.f);
            mu1 = su1 * (1.f/128.f);
            rs0 = rsqrtf(fmaxf(qu0 * (1.f/128.f) - mu0*mu0, 0.f) + 1e-5f);
            rs1 = rsqrtf(fmaxf(qu1 * (1.f/128.f) - mu1*mu1, 0.f) + 1e-5f);
        }
#pragma unroll
        for (int ni = 0; ni < 4; ++ni) {
            int ncol = wn * 32 + ni * 8 + t4 * 2;
            size_t ci0 = (size_t)(m0 + lr0) * Dx + ncol;
            size_t ci1 = (size_t)(m0 + lr1) * Dx + ncol;
            float y0, y1, y2, y3;
            if (lnw) {
                float w0 = lnw[ncol], w1 = lnw[ncol + 1];
                float bb0 = lnb[ncol], bb1 = lnb[ncol + 1];
                y0 = (acc[mi][ni][0] - mu0) * rs0 * w0 + bb0;
                y1 = (acc[mi][ni][1] - mu0) * rs0 * w1 + bb1;
                y2 = (acc[mi][ni][2] - mu1) * rs1 * w0 + bb0;
                y3 = (acc[mi][ni][3] - mu1) * rs1 * w1 + bb1;
            } else {
                y0 = acc[mi][ni][0]; y1 = acc[mi][ni][1];
                y2 = acc[mi][ni][2]; y3 = acc[mi][ni][3];
            }
            split_store(oh, ol, ci0, y0, y1);
            split_store(oh, ol, ci1, y2, y3);
        }
    }
}

// ---------------------------------------------------------------------------
// Pipelined tensor-core GEMM (K=128 resident-B, A double-buffered).
// EPI: 1=gelu(+bias)->bf16 planes; 2=Wo: bias+res+fused-LN (lnw/lnb in
// bias2/bias3, planes in Chh/Chl, full row per CTA); 5=fused QKV.
// ---------------------------------------------------------------------------
template <int EPI>
__global__ void __launch_bounds__(256) tgemm(
    const __nv_bfloat16* __restrict__ Ah, const __nv_bfloat16* __restrict__ Al, int lda,
    const __nv_bfloat16* __restrict__ Bh, const __nv_bfloat16* __restrict__ Bl,
    const float* __restrict__ bias, const float* __restrict__ bias2,
    const float* __restrict__ bias3, const float* __restrict__ res,
    float* __restrict__ Cf, float* __restrict__ Cf2, float* __restrict__ Cf3,
    __nv_bfloat16* __restrict__ Chh, __nv_bfloat16* __restrict__ Chl,
    int ldc, int mTiles)
{
    extern __shared__ char smraw[];
    uint32_t sb = smem_u32(smraw);
    const uint32_t sBh = sb, sBl = sb + PLANE;
    float* rsum = (float*)(smraw + 6 * PLANE);
    float* rsq  = rsum + 128 * 4;

    int tid = threadIdx.x, wid = tid >> 5, lane = tid & 31;
    int wm = wid >> 2, wn = wid & 3;
    int n0;
    if (EPI == 5) {
        n0 = 0;
        int sel = blockIdx.x;
        Bh  += sel * 16384;  Bl += sel * 16384;
        bias = (sel == 0) ? bias : (sel == 1) ? bias2 : bias3;
        Cf   = (sel == 0) ? Cf   : (sel == 1) ? Cf2   : Cf3;
    } else {
        n0 = blockIdx.x * 128;
    }
    int mt0 = blockIdx.y;

    stage_async(Bh + (size_t)n0 * lda, lda, sBh, tid);
    stage_async(Bl + (size_t)n0 * lda, lda, sBl, tid);
    if (mt0 < mTiles) {
        stage_async(Ah + (size_t)(mt0 * 128) * lda, lda, sb + 2 * PLANE, tid);
        stage_async(Al + (size_t)(mt0 * 128) * lda, lda, sb + 3 * PLANE, tid);
    }
    CP_COMMIT();
    CP_WAIT0();
    __syncthreads();

    const uint32_t aoff = ((wm * 64 + (lane & 15)) * PAD + (lane >> 4) * 8) * 2;
    const uint32_t boff = ((wn * 32 + ((lane >> 4) << 3) + (lane & 7)) * PAD
                          + ((lane >> 3) & 1) * 8) * 2;

    int buf = 0;
    for (int mt = mt0; mt < mTiles; mt += gridDim.y) {
        int m0 = mt * 128;
        int next = mt + gridDim.y;
        if (next < mTiles) {
            uint32_t nb = sb + (2 + 2 * (buf ^ 1)) * PLANE;
            stage_async(Ah + (size_t)(next * 128) * lda, lda, nb, tid);
            stage_async(Al + (size_t)(next * 128) * lda, lda, nb + PLANE, tid);
            CP_COMMIT();
        }
        const uint32_t sAh = sb + (2 + 2 * buf) * PLANE, sAl = sAh + PLANE;

        float acc[4][4][4];
#pragma unroll
        for (int mi = 0; mi < 4; ++mi)
#pragma unroll
            for (int ni = 0; ni < 4; ++ni)
#pragma unroll
                for (int e = 0; e < 4; ++e) acc[mi][ni][e] = 0.f;

        mma_chunk(acc, sAh, sAl, sBh, sBl, aoff, boff);

        if (EPI == 2) {
            epi_ln_split(acc, bias, res, Cf, bias2, bias3, Chh, Chl,
                         rsum, rsq, m0, wm, wn, lane);
        } else {
            int gp = lane >> 2, t4 = lane & 3;
#pragma unroll
            for (int mi = 0; mi < 4; ++mi) {
                int mrow = m0 + wm * 64 + mi * 16 + gp;
#pragma unroll
                for (int ni = 0; ni < 4; ++ni) {
                    int ncol = n0 + wn * 32 + ni * 8 + t4 * 2;
                    float d0 = acc[mi][ni][0], d1 = acc[mi][ni][1];
                    float d2 = acc[mi][ni][2], d3 = acc[mi][ni][3];
                    float b0 = bias[ncol], b1 = bias[ncol + 1];
                    d0 += b0; d1 += b1; d2 += b0; d3 += b1;
                    size_t ci0 = (size_t)mrow * ldc + ncol;
                    size_t ci1 = (size_t)(mrow + 8) * ldc + ncol;
                    if (EPI == 1) {
                        d0 = 0.5f * d0 * (1.f + erff(d0 * 0.7071067811865476f));
                        d1 = 0.5f * d1 * (1.f + erff(d1 * 0.7071067811865476f));
                        d2 = 0.5f * d2 * (1.f + erff(d2 * 0.7071067811865476f));
                        d3 = 0.5f * d3 * (1.f + erff(d3 * 0.7071067811865476f));
                        split_store(Chh, Chl, ci0, d0, d1);
                        split_store(Chh, Chl, ci1, d2, d3);
                    } else {
                        *(float2*)(Cf + ci0) = make_float2(d0, d1);
                        *(float2*)(Cf + ci1) = make_float2(d2, d3);
                    }
                }
            }
        }
        if (next < mTiles) CP_WAIT0();
        __syncthreads();
        buf ^= 1;
    }
}

// ---------------------------------------------------------------------------
// W2 GEMM (K=512): 8 pipelined K=64 chunks; fused bias+res + LN/split epilogue.
// ---------------------------------------------------------------------------
__global__ void __launch_bounds__(256) tgemm_w2(
    const __nv_bfloat16* __restrict__ Ah, const __nv_bfloat16* __restrict__ Al,
    const __nv_bfloat16* __restrict__ Bh, const __nv_bfloat16* __restrict__ Bl,
    const float* __restrict__ bias, const float* __restrict__ res,
    float* __restrict__ Cf,
    const float* __restrict__ lnw, const float* __restrict__ lnb,
    __nv_bfloat16* __restrict__ oh, __nv_bfloat16* __restrict__ ol,
    int mTiles)
{
    extern __shared__ char smraw[];
    uint32_t sb = smem_u32(smraw);
    float* rsum = (float*)(smraw + 8 * HPLANE);
    float* rsq  = rsum + 128 * 4;
    const int lda = FFx;

    int tid = threadIdx.x, wid = tid >> 5, lane = tid & 31;
    int wm = wid >> 2, wn = wid & 3;

    const uint32_t aoff = ((wm * 64 + (lane & 15)) * PAD2 + (lane >> 4) * 8) * 2;
    const uint32_t boff = ((wn * 32 + ((lane >> 4) << 3) + (lane & 7)) * PAD2
                          + ((lane >> 3) & 1) * 8) * 2;

    for (int mt = blockIdx.y; mt < mTiles; mt += gridDim.y) {
        int m0 = mt * 128;
        float acc[4][4][4];
#pragma unroll
        for (int mi = 0; mi < 4; ++mi)
#pragma unroll
            for (int ni = 0; ni < 4; ++ni)
#pragma unroll
                for (int e = 0; e < 4; ++e) acc[mi][ni][e] = 0.f;

        stage_async64(Ah + (size_t)m0 * lda, lda, sb + 0 * HPLANE, tid);
        stage_async64(Al + (size_t)m0 * lda, lda, sb + 1 * HPLANE, tid);
        stage_async64(Bh,                    lda, sb + 2 * HPLANE, tid);
        stage_async64(Bl,                    lda, sb + 3 * HPLANE, tid);
        CP_COMMIT();
        CP_WAIT0();
        __syncthreads();

        int buf = 0;
        for (int c = 0; c < 8; ++c) {
            if (c + 1 < 8) {
                uint32_t nb = sb + (buf ^ 1) * 4 * HPLANE;
                int ko = (c + 1) * 64;
                stage_async64(Ah + (size_t)m0 * lda + ko, lda, nb,              tid);
                stage_async64(Al + (size_t)m0 * lda + ko, lda, nb + HPLANE,     tid);
                stage_async64(Bh + ko,                    lda, nb + 2 * HPLANE, tid);
                stage_async64(Bl + ko,                    lda, nb + 3 * HPLANE, tid);
                CP_COMMIT();
            }
            uint32_t cb = sb + buf * 4 * HPLANE;
            mma_chunk64(acc, cb, cb + HPLANE, cb + 2 * HPLANE, cb + 3 * HPLANE, aoff, boff);
            if (c + 1 < 8) CP_WAIT0();
            __syncthreads();
            buf ^= 1;
        }

        epi_ln_split(acc, bias, res, Cf, lnw, lnb, oh, ol,
                     rsum, rsq, m0, wm, wn, lane);
        __syncthreads();
    }
}

// ---------------------------------------------------------------------------
// Final FC on tensor path
// ---------------------------------------------------------------------------
__global__ void __launch_bounds__(256) tgemm_fc(
    const __nv_bfloat16* __restrict__ Ah, const __nv_bfloat16* __restrict__ Al,
    const __nv_bfloat16* __restrict__ Bh, const __nv_bfloat16* __restrict__ Bl,
    float* __restrict__ part)
{
    extern __shared__ char smraw[];
    uint32_t sb = smem_u32(smraw);
    const int lda = FCK;

    int tid = threadIdx.x, wid = tid >> 5, lane = tid & 31;
    int wm = wid >> 2, wn = wid & 3;
    int m0 = blockIdx.x * 128;
    int kbase = blockIdx.y * 1024;

    const uint32_t aoff = ((wm * 64 + (lane & 15)) * PAD2 + (lane >> 4) * 8) * 2;
    const uint32_t boff = ((wn * 32 + ((lane >> 4) << 3) + (lane & 7)) * PAD2
                          + ((lane >> 3) & 1) * 8) * 2;

    float acc[4][4][4];
#pragma unroll
    for (int mi = 0; mi < 4; ++mi)
#pragma unroll
        for (int ni = 0; ni < 4; ++ni)
#pragma unroll
            for (int e = 0; e < 4; ++e) acc[mi][ni][e] = 0.f;

    stage_async64(Ah + (size_t)m0 * lda + kbase, lda, sb + 0 * HPLANE, tid);
    stage_async64(Al + (size_t)m0 * lda + kbase, lda, sb + 1 * HPLANE, tid);
    stage_async64(Bh + kbase,                    lda, sb + 2 * HPLANE, tid);
    stage_async64(Bl + kbase,                    lda, sb + 3 * HPLANE, tid);
    CP_COMMIT();
    CP_WAIT0();
    __syncthreads();

    int buf = 0;
    for (int c = 0; c < 16; ++c) {
        if (c + 1 < 16) {
            uint32_t nb = sb + (buf ^ 1) * 4 * HPLANE;
            int ko = kbase + (c + 1) * 64;
            stage_async64(Ah + (size_t)m0 * lda + ko, lda, nb,              tid);
            stage_async64(Al + (size_t)m0 * lda + ko, lda, nb + HPLANE,     tid);
            stage_async64(Bh + ko,                    lda, nb + 2 * HPLANE, tid);
            stage_async64(Bl + ko,                    lda, nb + 3 * HPLANE, tid);
            CP_COMMIT();
        }
        uint32_t cb = sb + buf * 4 * HPLANE;
        mma_chunk64(acc, cb, cb + HPLANE, cb + 2 * HPLANE, cb + 3 * HPLANE, aoff, boff);
        if (c + 1 < 16) CP_WAIT0();
        __syncthreads();
        buf ^= 1;
    }

    float* Cp = part + (size_t)blockIdx.y * Bx * Dx;
    int gp = lane >> 2, t4 = lane & 3;
#pragma unroll
    for (int mi = 0; mi < 4; ++mi) {
        int mrow = m0 + wm * 64 + mi * 16 + gp;
#pragma unroll
        for (int ni = 0; ni < 4; ++ni) {
            int ncol = wn * 32 + ni * 8 + t4 * 2;
            *(float2*)(Cp + (size_t)mrow * Dx + ncol) =
                make_float2(acc[mi][ni][0], acc[mi][ni][1]);
            *(float2*)(Cp + (size_t)(mrow + 8) * Dx + ncol) =
                make_float2(acc[mi][ni][2], acc[mi][ni][3]);
        }
    }
}

__global__ void fcred_k(const float* __restrict__ part, const float* __restrict__ bias,
                        float* __restrict__ out) {
    int idx = blockIdx.x * 256 + threadIdx.x;
    if (idx >= Bx * Dx) return;
    float s = 0.f;
#pragma unroll
    for (int z = 0; z < FCZ; ++z) s += part[(size_t)z * Bx * Dx + idx];
    out[idx] = s + bias[idx & (Dx - 1)];
}

// ---------------------------------------------------------------------------
// Fused masked attention (R14-proven version: float4 smem, __expf)
// ---------------------------------------------------------------------------
#define AKS 36
#define AVS 204
#define ATTN_SMEM_FLOATS (200*AKS + 32*AVS + 200 + 8*2*AVS)
#define ATTN_SMEM_BYTES  (ATTN_SMEM_FLOATS * 4)

__global__ void __launch_bounds__(256) attn_k(
    const float* __restrict__ Q, const float* __restrict__ Kx,
    const float* __restrict__ Vx, const int* __restrict__ seqs,
    __nv_bfloat16* __restrict__ Oh, __nv_bfloat16* __restrict__ Ol)
{
    int h = blockIdx.x, b = blockIdx.y;
    extern __shared__ float sm[];
    float* Ks   = sm;
    float* Vt   = Ks + 200 * AKS;
    float* flag = Vt + 32 * AVS;
    float* ps   = flag + 200;

    int tid = threadIdx.x;
    size_t base = ((size_t)b * Lx) * Dx + h * DKx;

    for (int idx = tid; idx < 1600; idx += 256) {
        int l = idx >> 3, i = idx & 7;
        float4 v = *(const float4*)(Kx + base + (size_t)l * Dx + i * 4);
        *(float4*)(Ks + l * AKS + i * 4) = v;
    }
    for (int idx = tid; idx < 6400; idx += 256) {
        int l = idx >> 5, d = idx & 31;
        Vt[d * AVS + l] = Vx[base + (size_t)l * Dx + d];
    }
    for (int l = tid; l < 200; l += 256)
        flag[l] = (seqs[b * Lx + l] > 0) ? 1.f : 0.f;
    __syncthreads();

    int warp = tid >> 5, lane = tid & 31;
    float* psw = ps + warp * 2 * AVS;
    const float scale = 0.17677669529663687f;

    for (int qp = warp; qp < 100; qp += 8) {
        int q0 = qp, q1 = qp + 100;
        float4 qa[8], qb[8];
        const float4* q0p = (const float4*)(Q + base + (size_t)q0 * Dx);
        const float4* q1p = (const float4*)(Q + base + (size_t)q1 * Dx);
#pragma unroll
        for (int i = 0; i < 8; ++i) { qa[i] = q0p[i]; qb[i] = q1p[i]; }

        float s0[7], s1[7], mx0 = -1e30f, mx1 = -1e30f;
#pragma unroll
        for (int j = 0; j < 7; ++j) {
            int k = j * 32 + lane;
            const float* kr = Ks + k * AKS;
            float d0 = 0.f, d1 = 0.f;
#pragma unroll
            for (int i = 0; i < 8; ++i) {
                float4 kv = *(const float4*)(kr + i * 4);
                d0 = fmaf(qa[i].x, kv.x, d0); d0 = fmaf(qa[i].y, kv.y, d0);
                d0 = fmaf(qa[i].z, kv.z, d0); d0 = fmaf(qa[i].w, kv.w, d0);
                d1 = fmaf(qb[i].x, kv.x, d1); d1 = fmaf(qb[i].y, kv.y, d1);
                d1 = fmaf(qb[i].z, kv.z, d1); d1 = fmaf(qb[i].w, kv.w, d1);
            }
            bool valid = (k < 200);
            float fl = valid ? flag[k] : 0.f;
            float v0 = (fl != 0.f) ? d0 * scale : -1e9f;
            float v1 = (fl != 0.f) ? d1 * scale : -1e9f;
            s0[j] = valid ? v0 : -1e30f;
            s1[j] = valid ? v1 : -1e30f;
            mx0 = fmaxf(mx0, s0[j]);
            mx1 = fmaxf(mx1, s1[j]);
        }
#pragma unroll
        for (int o = 16; o; o >>= 1) {
            mx0 = fmaxf(mx0, __shfl_xor_sync(~0u, mx0, o));
            mx1 = fmaxf(mx1, __shfl_xor_sync(~0u, mx1, o));
        }

        float p0[7], p1[7], sum0 = 0.f, sum1 = 0.f;
#pragma unroll
        for (int j = 0; j < 7; ++j) {
            p0[j] = __expf(s0[j] - mx0); sum0 += p0[j];
            p1[j] = __expf(s1[j] - mx1); sum1 += p1[j];
        }
#pragma unroll
        for (int o = 16; o; o >>= 1) {
            sum0 += __shfl_xor_sync(~0u, sum0, o);
            sum1 += __shfl_xor_sync(~0u, sum1, o);
        }
        float inv0 = 1.f / sum0, inv1 = 1.f / sum1;

#pragma unroll
        for (int j = 0; j < 7; ++j) {
            int k = j * 32 + lane;
            if (k < 200) { psw[k] = p0[j]; psw[AVS + k] = p1[j]; }
        }
        __syncwarp();

        float a0 = 0.f, a1 = 0.f;
        const float* vr = Vt + lane * AVS;
#pragma unroll
        for (int kg = 0; kg < 50; ++kg) {
            float4 pv0 = *(const float4*)(psw + kg * 4);
            float4 pv1 = *(const float4*)(psw + AVS + kg * 4);
            float4 vv  = *(const float4*)(vr + kg * 4);
            a0 = fmaf(pv0.x, vv.x, a0); a0 = fmaf(pv0.y, vv.y, a0);
            a0 = fmaf(pv0.z, vv.z, a0); a0 = fmaf(pv0.w, vv.w, a0);
            a1 = fmaf(pv1.x, vv.x, a1); a1 = fmaf(pv1.y, vv.y, a1);
            a1 = fmaf(pv1.z, vv.z, a1); a1 = fmaf(pv1.w, vv.w, a1);
        }
        float vo0 = a0 * inv0, vo1 = a1 * inv1;
        split_store(Oh, Ol, base + (size_t)q0 * Dx + lane - (lane & 1), 0, 0); // placeholder no
        // scalar store (lane-granular, can't pair):
        {
            __nv_bfloat16 h0 = __float2bfloat16(vo0), h1 = __float2bfloat16(vo1);
            Oh[base + (size_t)q0 * Dx + lane] = h0;
            Ol[base + (size_t)q0 * Dx + lane] = __float2bfloat16(vo0 - __bfloat162float(h0));
            Oh[base + (size_t)q1 * Dx + lane] = h1;
            Ol[base + (size_t)q1 * Dx + lane] = __float2bfloat16(vo1 - __bfloat162float(h1));
        }
        __syncwarp();
    }
}

// ---------------------------------------------------------------------------
// Host driver
// ---------------------------------------------------------------------------
extern "C" void kernel_launch(void* const* d_in, const int* in_sizes, int n_in,
                              void* d_out, int out_size) {
    (void)in_sizes; (void)n_in; (void)out_size;
    const int*   seqs = (const int*)  d_in[0];
    const float* tok  = (const float*)d_in[1];
    const float* pos  = (const float*)d_in[2];
    const float* Wq   = (const float*)d_in[3];
    const float* bq   = (const float*)d_in[4];
    const float* Wk   = (const float*)d_in[5];
    const float* bk   = (const float*)d_in[6];
    const float* Wv   = (const float*)d_in[7];
    const float* bv   = (const float*)d_in[8];
    const float* Wo   = (const float*)d_in[9];
    const float* bo   = (const float*)d_in[10];
    const float* ln1w = (const float*)d_in[11];
    const float* ln1b = (const float*)d_in[12];
    const float* ln2w = (const float*)d_in[13];
    const float* ln2b = (const float*)d_in[14];
    const float* W1   = (const float*)d_in[15];
    const float* b1   = (const float*)d_in[16];
    const float* W2   = (const float*)d_in[17];
    const float* b2   = (const float*)d_in[18];
    const float* fcW  = (const float*)d_in[19];
    const float* fcb  = (const float*)d_in[20];
    float* out = (float*)d_out;

    float *px, *pq, *pk, *pv, *pp;
    __nv_bfloat16 *ah, *al, *oh, *ol, *fh, *fl, *wh, *wl, *fwh, *fwl;
    cudaGetSymbolAddress((void**)&px, g_x);
    cudaGetSymbolAddress((void**)&pq, g_q);
    cudaGetSymbolAddress((void**)&pk, g_k);
    cudaGetSymbolAddress((void**)&pv, g_v);
    cudaGetSymbolAddress((void**)&pp, g_fcp);
    cudaGetSymbolAddress((void**)&ah, g_ah);
    cudaGetSymbolAddress((void**)&al, g_al);
    cudaGetSymbolAddress((void**)&oh, g_oh);
    cudaGetSymbolAddress((void**)&ol, g_ol);
    cudaGetSymbolAddress((void**)&fh, g_fh);
    cudaGetSymbolAddress((void**)&fl, g_fl);
    cudaGetSymbolAddress((void**)&wh, g_wh);
    cudaGetSymbolAddress((void**)&wl, g_wl);
    cudaGetSymbolAddress((void**)&fwh, g_fcwh);
    cudaGetSymbolAddress((void**)&fwl, g_fcwl);

    cudaFuncSetAttribute(attn_k, cudaFuncAttributeMaxDynamicSharedMemorySize, ATTN_SMEM_BYTES);
    cudaFuncSetAttribute(tgemm<1>, cudaFuncAttributeMaxDynamicSharedMemorySize, TG_SMEM);
    cudaFuncSetAttribute(tgemm<2>, cudaFuncAttributeMaxDynamicSharedMemorySize, TG_SMEM_LN);
    cudaFuncSetAttribute(tgemm<5>, cudaFuncAttributeMaxDynamicSharedMemorySize, TG_SMEM);
    cudaFuncSetAttribute(tgemm_w2, cudaFuncAttributeMaxDynamicSharedMemorySize, W2_SMEM_LN);
    cudaFuncSetAttribute(tgemm_fc, cudaFuncAttributeMaxDynamicSharedMemorySize, FC_SMEM);

    wconv_all<<<(NLx * LW + 255) / 256, 256>>>(Wq, Wk, Wv, Wo, W1, W2, wh, wl);
    wconv_fc<<<(Dx * FCK + 255) / 256, 256>>>(fcW, fwh, fwl);

    const dim3 gRow(NT / 8);
    const int  MT = NT / 128;  // 1600

    embed_k<<<gRow, 256>>>(seqs, tok, pos, px);
    ln_k<<<gRow, 256>>>(px, ln1w, ln1b, ah, al);   // layer 0 ln1 only

    for (int i = 0; i < NLx; ++i) {
        size_t wb = (size_t)i * LW;
        // --- attention block ---
        tgemm<5><<<dim3(3,148), 256, TG_SMEM>>>(ah, al, Dx, wh + wb, wl + wb,
                 bq + i*Dx, bk + i*Dx, bv + i*Dx, nullptr,
                 pq, pk, pv, nullptr, nullptr, Dx, MT);
        attn_k<<<dim3(Hx, Bx), 256, ATTN_SMEM_BYTES>>>(pq, pk, pv, seqs, oh, ol);
        // Wo GEMM + residual + fused LN2 -> planes for W1
        tgemm<2><<<dim3(1,148), 256, TG_SMEM_LN>>>(oh, ol, Dx,
                 wh + wb + 49152, wl + wb + 49152,
                 bo + i*Dx, ln2w + i*Dx, ln2b + i*Dx, px,
                 px, nullptr, nullptr, ah, al, Dx, MT);
        // --- FFN block ---
        tgemm<1><<<dim3(4,37), 256, TG_SMEM>>>(ah, al, Dx, wh + wb + 65536, wl + wb + 65536,
                 b1 + i*FFx, nullptr, nullptr, nullptr,
                 nullptr, nullptr, nullptr, fh, fl, FFx, MT);
        // W2 GEMM + residual + fused LN1(next) or plain split (last layer)
        const float* nlw = (i + 1 < NLx) ? (ln1w + (i + 1) * Dx) : nullptr;
        const float* nlb = (i + 1 < NLx) ? (ln1b + (i + 1) * Dx) : nullptr;
        tgemm_w2<<<dim3(1,148), 256, W2_SMEM_LN>>>(fh, fl,
                 wh + wb + 131072, wl + wb + 131072,
                 b2 + i*Dx, px, px, nlw, nlb, ah, al, MT);
    }

    // Final FC on tensor path (planes already produced by last W2 epilogue)
    tgemm_fc<<<dim3(Bx / 128, FCZ), 256, FC_SMEM>>>(ah, al, fwh, fwl, pp);
    fcred_k<<<(Bx * Dx + 255) / 256, 256>>>(pp, fcb, out);
}

// round 17
// speedup vs baseline: 1.3880x; 1.3880x over previous
#include <cuda_runtime.h>
#include <cuda_fp16.h>
#include <math.h>
#include <stdint.h>

// Problem constants
#define Bx   1024
#define Lx   200
#define Dx   128
#define Hx   4
#define DKx  32
#define FFx  512
#define NLx  2
#define NT   (Bx*Lx)          // 204800 tokens
#define FCK  (Lx*Dx)          // 25600
#define FCZ  25               // FC K-split

// ---------------------------------------------------------------------------
// Device-global scratch (allocation-free rule).
// ---------------------------------------------------------------------------
__device__ float g_x  [(size_t)NT * Dx];    // residual stream (fp32)
__device__ float g_q  [(size_t)NT * Dx];
__device__ float g_k  [(size_t)NT * Dx];
__device__ float g_v  [(size_t)NT * Dx];
__device__ float g_fcp[(size_t)32 * Bx * Dx];

// fp16 activation planes (single plane; fp16 quantization ~2^-11)
__device__ __half g_a[(size_t)NT * Dx];     // LN out / FC input plane
__device__ __half g_o[(size_t)NT * Dx];     // attn out
__device__ __half g_f[(size_t)NT * FFx];    // FFN mid

// transposed fp16 weights [N][K]
#define LW 196608
__device__ __half g_w[(size_t)NLx * LW];
__device__ __half g_fcw[(size_t)Dx * FCK];

// ---------------------------------------------------------------------------
// Helpers
// ---------------------------------------------------------------------------
__device__ __forceinline__ uint32_t smem_u32(const void* p) {
    uint32_t a;
    asm("{ .reg .u64 t; cvta.to.shared.u64 t, %1; cvt.u32.u64 %0, t; }" : "=r"(a) : "l"(p));
    return a;
}
__device__ __forceinline__ void ldm4(uint32_t* r, uint32_t addr) {
    asm volatile("ldmatrix.sync.aligned.m8n8.x4.shared.b16 {%0,%1,%2,%3}, [%4];"
                 : "=r"(r[0]), "=r"(r[1]), "=r"(r[2]), "=r"(r[3]) : "r"(addr));
}
__device__ __forceinline__ void mma_f16(float* d, const uint32_t* a, const uint32_t* b) {
    asm volatile("mma.sync.aligned.m16n8k16.row.col.f32.f16.f16.f32 "
                 "{%0,%1,%2,%3}, {%4,%5,%6,%7}, {%8,%9}, {%0,%1,%2,%3};"
                 : "+f"(d[0]), "+f"(d[1]), "+f"(d[2]), "+f"(d[3])
                 : "r"(a[0]), "r"(a[1]), "r"(a[2]), "r"(a[3]), "r"(b[0]), "r"(b[1]));
}
#define CP_COMMIT() asm volatile("cp.async.commit_group;" ::: "memory")
#define CP_WAIT0()  asm volatile("cp.async.wait_group 0;" ::: "memory")

__device__ __forceinline__ void hstore2(__half* o, size_t ci, float y0, float y1) {
    *(half2*)(o + ci) = __floats2half2_rn(y0, y1);
}

// ---------------------------------------------------------------------------
// Weight transpose + fp16 convert (single launch, all layer weights)
// ---------------------------------------------------------------------------
__global__ void wconv_all(const float* __restrict__ Wq, const float* __restrict__ Wk,
                          const float* __restrict__ Wv, const float* __restrict__ Wo,
                          const float* __restrict__ W1, const float* __restrict__ W2,
                          __half* __restrict__ T) {
    int idx = blockIdx.x * 256 + threadIdx.x;
    if (idx >= NLx * LW) return;
    int l = idx / LW, o = idx % LW;
    float v;
    if (o < 65536) {
        int seg = o >> 14, loc = o & 16383;
        int n = loc >> 7, k = loc & 127;
        const float* W = (seg == 0) ? Wq : (seg == 1) ? Wk : (seg == 2) ? Wv : Wo;
        v = W[(size_t)l * Dx * Dx + k * Dx + n];
    } else if (o < 131072) {
        int loc = o - 65536;
        int n = loc >> 7, k = loc & 127;
        v = W1[(size_t)l * Dx * FFx + k * FFx + n];
    } else {
        int loc = o - 131072;
        int n = loc >> 9, k = loc & 511;
        v = W2[(size_t)l * FFx * Dx + k * Dx + n];
    }
    T[idx] = __float2half_rn(v);
}

__global__ void wconv_fc(const float* __restrict__ W, __half* __restrict__ T) {
    int idx = blockIdx.x * 256 + threadIdx.x;
    if (idx >= Dx * FCK) return;
    int n = idx / FCK, k = idx % FCK;
    T[idx] = __float2half_rn(W[(size_t)k * Dx + n]);
}

// ---------------------------------------------------------------------------
// Embedding
// ---------------------------------------------------------------------------
__global__ void embed_k(const int* __restrict__ seqs, const float* __restrict__ tok,
                        const float* __restrict__ pos, float* __restrict__ x) {
    int t = blockIdx.x * 8 + (threadIdx.x >> 5);
    int lane = threadIdx.x & 31;
    if (t >= NT) return;
    int id = seqs[t], l = t % Lx;
    float4 te = *(const float4*)(tok + (size_t)id * Dx + lane * 4);
    float4 pe = *(const float4*)(pos + (size_t)l  * Dx + lane * 4);
    *(float4*)(x + (size_t)t * Dx + lane * 4) =
        make_float4(te.x + pe.x, te.y + pe.y, te.z + pe.z, te.w + pe.w);
}

// ---------------------------------------------------------------------------
// Standalone LayerNorm -> fp16 plane (layer 0 ln1 only)
// ---------------------------------------------------------------------------
__global__ void ln_k(const float* __restrict__ x, const float* __restrict__ w,
                     const float* __restrict__ b, __half* __restrict__ oh) {
    int r = blockIdx.x * 8 + (threadIdx.x >> 5);
    int lane = threadIdx.x & 31;
    if (r >= NT) return;
    float4 v = *(const float4*)(x + (size_t)r * Dx + lane * 4);
    float s = v.x + v.y + v.z + v.w;
#pragma unroll
    for (int o = 16; o; o >>= 1) s += __shfl_xor_sync(~0u, s, o);
    float mu = s * (1.f / 128.f);
    float dx = v.x - mu, dy = v.y - mu, dz = v.z - mu, dw = v.w - mu;
    float s2 = dx*dx + dy*dy + dz*dz + dw*dw;
#pragma unroll
    for (int o = 16; o; o >>= 1) s2 += __shfl_xor_sync(~0u, s2, o);
    float rs = rsqrtf(s2 * (1.f / 128.f) + 1e-5f);
    float4 wv = *(const float4*)(w + lane * 4);
    float4 bv = *(const float4*)(b + lane * 4);
    size_t o = (size_t)r * Dx + lane * 4;
    hstore2(oh, o,     dx*rs*wv.x + bv.x, dy*rs*wv.y + bv.y);
    hstore2(oh, o + 2, dz*rs*wv.z + bv.z, dw*rs*wv.w + bv.w);
}

// ---------------------------------------------------------------------------
// GEMM tiles/layout
// ---------------------------------------------------------------------------
#define PAD 136
#define PLANE (128 * PAD * 2)        // 34816 bytes
#define LNRED (128 * 4 * 2 * 4)      // 4096 bytes
#define TG_SMEM    (3 * PLANE)               // 104448
#define TG_SMEM_LN (3 * PLANE + LNRED)       // 108544
#define PAD2 72
#define HPLANE (128 * PAD2 * 2)      // 18432 bytes
#define W2_SMEM_LN (4 * HPLANE + LNRED)      // 77824
#define FC_SMEM    (4 * HPLANE)              // 73728

__device__ __forceinline__ void stage_async(const __half* __restrict__ src, int ld,
                                            uint32_t smbase, int tid) {
#pragma unroll
    for (int it = 0; it < 8; ++it) {
        int i = it * 256 + tid;
        int row = i >> 4, seg = (i & 15) << 3;
        uint32_t dst = smbase + (row * PAD + seg) * 2;
        asm volatile("cp.async.cg.shared.global [%0], [%1], 16;"
                     :: "r"(dst), "l"(src + (size_t)row * ld + seg) : "memory");
    }
}
__device__ __forceinline__ void stage_async64(const __half* __restrict__ src, int ld,
                                              uint32_t smbase, int tid) {
#pragma unroll
    for (int it = 0; it < 4; ++it) {
        int i = it * 256 + tid;
        int row = i >> 3, seg = (i & 7) << 3;
        uint32_t dst = smbase + (row * PAD2 + seg) * 2;
        asm volatile("cp.async.cg.shared.global [%0], [%1], 16;"
                     :: "r"(dst), "l"(src + (size_t)row * ld + seg) : "memory");
    }
}

__device__ __forceinline__ void mma_chunk(
    float acc[4][4][4], uint32_t sA, uint32_t sB, uint32_t aoff, uint32_t boff)
{
#pragma unroll
    for (int ks = 0; ks < 8; ++ks) {
        uint32_t kb = ks * 32;
        uint32_t fa[4][4], fb[4][2];
#pragma unroll
        for (int mi = 0; mi < 4; ++mi)
            ldm4(fa[mi], sA + aoff + mi * 16 * PAD * 2 + kb);
#pragma unroll
        for (int np = 0; np < 2; ++np)
            ldm4(&fb[2 * np][0], sB + boff + np * 16 * PAD * 2 + kb);
#pragma unroll
        for (int mi = 0; mi < 4; ++mi)
#pragma unroll
            for (int ni = 0; ni < 4; ++ni)
                mma_f16(acc[mi][ni], fa[mi], fb[ni]);
    }
}
__device__ __forceinline__ void mma_chunk64(
    float acc[4][4][4], uint32_t sA, uint32_t sB, uint32_t aoff, uint32_t boff)
{
#pragma unroll
    for (int ks = 0; ks < 4; ++ks) {
        uint32_t kb = ks * 32;
        uint32_t fa[4][4], fb[4][2];
#pragma unroll
        for (int mi = 0; mi < 4; ++mi)
            ldm4(fa[mi], sA + aoff + mi * 16 * PAD2 * 2 + kb);
#pragma unroll
        for (int np = 0; np < 2; ++np)
            ldm4(&fb[2 * np][0], sB + boff + np * 16 * PAD2 * 2 + kb);
#pragma unroll
        for (int mi = 0; mi < 4; ++mi)
#pragma unroll
            for (int ni = 0; ni < 4; ++ni)
                mma_f16(acc[mi][ni], fa[mi], fb[ni]);
    }
}

// ---------------------------------------------------------------------------
// Fused epilogue: bias+res -> Cf (fp32); then LN (or plain convert if
// lnw==nullptr) -> fp16 plane oh. Requires full 128-wide row per CTA.
// ---------------------------------------------------------------------------
__device__ __forceinline__ void epi_ln_split(
    float acc[4][4][4], const float* __restrict__ bias, const float* __restrict__ res,
    float* __restrict__ Cf, const float* __restrict__ lnw, const float* __restrict__ lnb,
    __half* __restrict__ oh, float* rsum, float* rsq, int m0, int wm, int wn, int lane)
{
    int gp = lane >> 2, t4 = lane & 3;
    float s8[8], q8[8];
#pragma unroll
    for (int mi = 0; mi < 4; ++mi) {
        float s0 = 0.f, q0 = 0.f, s1 = 0.f, q1 = 0.f;
        int r0 = m0 + wm * 64 + mi * 16 + gp;
#pragma unroll
        for (int ni = 0; ni < 4; ++ni) {
            int ncol = wn * 32 + ni * 8 + t4 * 2;
            float b0 = bias[ncol], b1 = bias[ncol + 1];
            size_t ci0 = (size_t)r0 * Dx + ncol, ci1 = ci0 + 8 * Dx;
            float2 rv0 = *(const float2*)(res + ci0);
            float2 rv1 = *(const float2*)(res + ci1);
            float d0 = acc[mi][ni][0] + b0 + rv0.x;
            float d1 = acc[mi][ni][1] + b1 + rv0.y;
            float d2 = acc[mi][ni][2] + b0 + rv1.x;
            float d3 = acc[mi][ni][3] + b1 + rv1.y;
            acc[mi][ni][0] = d0; acc[mi][ni][1] = d1;
            acc[mi][ni][2] = d2; acc[mi][ni][3] = d3;
            *(float2*)(Cf + ci0) = make_float2(d0, d1);
            *(float2*)(Cf + ci1) = make_float2(d2, d3);
            s0 += d0 + d1; q0 += d0 * d0 + d1 * d1;
            s1 += d2 + d3; q1 += d2 * d2 + d3 * d3;
        }
        s8[2*mi] = s0; q8[2*mi] = q0; s8[2*mi+1] = s1; q8[2*mi+1] = q1;
    }
    if (lnw) {
#pragma unroll
        for (int i = 0; i < 8; ++i) {
            s8[i] += __shfl_xor_sync(~0u, s8[i], 1);
            s8[i] += __shfl_xor_sync(~0u, s8[i], 2);
            q8[i] += __shfl_xor_sync(~0u, q8[i], 1);
            q8[i] += __shfl_xor_sync(~0u, q8[i], 2);
        }
        if (t4 == 0) {
#pragma unroll
            for (int mi = 0; mi < 4; ++mi) {
                int lr = wm * 64 + mi * 16 + gp;
                rsum[lr * 4 + wn]       = s8[2*mi];
                rsq [lr * 4 + wn]       = q8[2*mi];
                rsum[(lr + 8) * 4 + wn] = s8[2*mi+1];
                rsq [(lr + 8) * 4 + wn] = q8[2*mi+1];
            }
        }
        __syncthreads();
    }
#pragma unroll
    for (int mi = 0; mi < 4; ++mi) {
        int lr0 = wm * 64 + mi * 16 + gp, lr1 = lr0 + 8;
        float mu0 = 0.f, rs0 = 0.f, mu1 = 0.f, rs1 = 0.f;
        if (lnw) {
            float su0 = rsum[lr0*4] + rsum[lr0*4+1] + rsum[lr0*4+2] + rsum[lr0*4+3];
            float qu0 = rsq [lr0*4] + rsq [lr0*4+1] + rsq [lr0*4+2] + rsq [lr0*4+3];
            float su1 = rsum[lr1*4] + rsum[lr1*4+1] + rsum[lr1*4+2] + rsum[lr1*4+3];
            float qu1 = rsq [lr1*4] + rsq [lr1*4+1] + rsq [lr1*4+2] + rsq [lr1*4+3];
            mu0 = su0 * (1.f/128.f);
            mu1 = su1 * (1.f/128.f);
            rs0 = rsqrtf(fmaxf(qu0 * (1.f/128.f) - mu0*mu0, 0.f) + 1e-5f);
            rs1 = rsqrtf(fmaxf(qu1 * (1.f/128.f) - mu1*mu1, 0.f) + 1e-5f);
        }
#pragma unroll
        for (int ni = 0; ni < 4; ++ni) {
            int ncol = wn * 32 + ni * 8 + t4 * 2;
            size_t ci0 = (size_t)(m0 + lr0) * Dx + ncol;
            size_t ci1 = (size_t)(m0 + lr1) * Dx + ncol;
            float y0, y1, y2, y3;
            if (lnw) {
                float w0 = lnw[ncol], w1 = lnw[ncol + 1];
                float bb0 = lnb[ncol], bb1 = lnb[ncol + 1];
                y0 = (acc[mi][ni][0] - mu0) * rs0 * w0 + bb0;
                y1 = (acc[mi][ni][1] - mu0) * rs0 * w1 + bb1;
                y2 = (acc[mi][ni][2] - mu1) * rs1 * w0 + bb0;
                y3 = (acc[mi][ni][3] - mu1) * rs1 * w1 + bb1;
            } else {
                y0 = acc[mi][ni][0]; y1 = acc[mi][ni][1];
                y2 = acc[mi][ni][2]; y3 = acc[mi][ni][3];
            }
            hstore2(oh, ci0, y0, y1);
            hstore2(oh, ci1, y2, y3);
        }
    }
}

// ---------------------------------------------------------------------------
// Pipelined fp16 tensor GEMM (K=128 resident-B, A double-buffered; 2 CTAs/SM).
// EPI: 1=gelu(+bias)->fp16 plane; 2=bias+res+fused-LN; 5=fused QKV (fp32 out).
// ---------------------------------------------------------------------------
template <int EPI>
__global__ void __launch_bounds__(256, 2) tgemm(
    const __half* __restrict__ Ah, int lda, const __half* __restrict__ Bh,
    const float* __restrict__ bias, const float* __restrict__ bias2,
    const float* __restrict__ bias3, const float* __restrict__ res,
    float* __restrict__ Cf, float* __restrict__ Cf2, float* __restrict__ Cf3,
    __half* __restrict__ Ch, int ldc, int mTiles)
{
    extern __shared__ char smraw[];
    uint32_t sb = smem_u32(smraw);
    const uint32_t sB = sb;
    float* rsum = (float*)(smraw + 3 * PLANE);
    float* rsq  = rsum + 128 * 4;

    int tid = threadIdx.x, wid = tid >> 5, lane = tid & 31;
    int wm = wid >> 2, wn = wid & 3;
    int n0;
    if (EPI == 5) {
        n0 = 0;
        int sel = blockIdx.x;
        Bh  += sel * 16384;
        bias = (sel == 0) ? bias : (sel == 1) ? bias2 : bias3;
        Cf   = (sel == 0) ? Cf   : (sel == 1) ? Cf2   : Cf3;
    } else {
        n0 = blockIdx.x * 128;
    }
    int mt0 = blockIdx.y;

    stage_async(Bh + (size_t)n0 * lda, lda, sB, tid);
    if (mt0 < mTiles)
        stage_async(Ah + (size_t)(mt0 * 128) * lda, lda, sb + PLANE, tid);
    CP_COMMIT();
    CP_WAIT0();
    __syncthreads();

    const uint32_t aoff = ((wm * 64 + (lane & 15)) * PAD + (lane >> 4) * 8) * 2;
    const uint32_t boff = ((wn * 32 + ((lane >> 4) << 3) + (lane & 7)) * PAD
                          + ((lane >> 3) & 1) * 8) * 2;

    int buf = 0;
    for (int mt = mt0; mt < mTiles; mt += gridDim.y) {
        int m0 = mt * 128;
        int next = mt + gridDim.y;
        if (next < mTiles) {
            stage_async(Ah + (size_t)(next * 128) * lda, lda,
                        sb + (1 + (buf ^ 1)) * PLANE, tid);
            CP_COMMIT();
        }
        const uint32_t sA = sb + (1 + buf) * PLANE;

        float acc[4][4][4];
#pragma unroll
        for (int mi = 0; mi < 4; ++mi)
#pragma unroll
            for (int ni = 0; ni < 4; ++ni)
#pragma unroll
                for (int e = 0; e < 4; ++e) acc[mi][ni][e] = 0.f;

        mma_chunk(acc, sA, sB, aoff, boff);

        if (EPI == 2) {
            epi_ln_split(acc, bias, res, Cf, bias2, bias3, Ch,
                         rsum, rsq, m0, wm, wn, lane);
        } else {
            int gp = lane >> 2, t4 = lane & 3;
#pragma unroll
            for (int mi = 0; mi < 4; ++mi) {
                int mrow = m0 + wm * 64 + mi * 16 + gp;
#pragma unroll
                for (int ni = 0; ni < 4; ++ni) {
                    int ncol = n0 + wn * 32 + ni * 8 + t4 * 2;
                    float d0 = acc[mi][ni][0], d1 = acc[mi][ni][1];
                    float d2 = acc[mi][ni][2], d3 = acc[mi][ni][3];
                    float b0 = bias[ncol], b1 = bias[ncol + 1];
                    d0 += b0; d1 += b1; d2 += b0; d3 += b1;
                    size_t ci0 = (size_t)mrow * ldc + ncol;
                    size_t ci1 = (size_t)(mrow + 8) * ldc + ncol;
                    if (EPI == 1) {
                        d0 = 0.5f * d0 * (1.f + erff(d0 * 0.7071067811865476f));
                        d1 = 0.5f * d1 * (1.f + erff(d1 * 0.7071067811865476f));
                        d2 = 0.5f * d2 * (1.f + erff(d2 * 0.7071067811865476f));
                        d3 = 0.5f * d3 * (1.f + erff(d3 * 0.7071067811865476f));
                        hstore2(Ch, ci0, d0, d1);
                        hstore2(Ch, ci1, d2, d3);
                    } else {
                        *(float2*)(Cf + ci0) = make_float2(d0, d1);
                        *(float2*)(Cf + ci1) = make_float2(d2, d3);
                    }
                }
            }
        }
        if (next < mTiles) CP_WAIT0();
        __syncthreads();
        buf ^= 1;
    }
}

// ---------------------------------------------------------------------------
// W2 GEMM (K=512): 8 pipelined K=64 chunks; fused bias+res + LN/convert.
// ---------------------------------------------------------------------------
__global__ void __launch_bounds__(256, 2) tgemm_w2(
    const __half* __restrict__ Ah, const __half* __restrict__ Bh,
    const float* __restrict__ bias, const float* __restrict__ res,
    float* __restrict__ Cf,
    const float* __restrict__ lnw, const float* __restrict__ lnb,
    __half* __restrict__ oh, int mTiles)
{
    extern __shared__ char smraw[];
    uint32_t sb = smem_u32(smraw);
    float* rsum = (float*)(smraw + 4 * HPLANE);
    float* rsq  = rsum + 128 * 4;
    const int lda = FFx;

    int tid = threadIdx.x, wid = tid >> 5, lane = tid & 31;
    int wm = wid >> 2, wn = wid & 3;

    const uint32_t aoff = ((wm * 64 + (lane & 15)) * PAD2 + (lane >> 4) * 8) * 2;
    const uint32_t boff = ((wn * 32 + ((lane >> 4) << 3) + (lane & 7)) * PAD2
                          + ((lane >> 3) & 1) * 8) * 2;

    for (int mt = blockIdx.y; mt < mTiles; mt += gridDim.y) {
        int m0 = mt * 128;
        float acc[4][4][4];
#pragma unroll
        for (int mi = 0; mi < 4; ++mi)
#pragma unroll
            for (int ni = 0; ni < 4; ++ni)
#pragma unroll
                for (int e = 0; e < 4; ++e) acc[mi][ni][e] = 0.f;

        stage_async64(Ah + (size_t)m0 * lda, lda, sb,          tid);
        stage_async64(Bh,                    lda, sb + HPLANE, tid);
        CP_COMMIT();
        CP_WAIT0();
        __syncthreads();

        int buf = 0;
        for (int c = 0; c < 8; ++c) {
            if (c + 1 < 8) {
                uint32_t nb = sb + (buf ^ 1) * 2 * HPLANE;
                int ko = (c + 1) * 64;
                stage_async64(Ah + (size_t)m0 * lda + ko, lda, nb,          tid);
                stage_async64(Bh + ko,                    lda, nb + HPLANE, tid);
                CP_COMMIT();
            }
            uint32_t cb = sb + buf * 2 * HPLANE;
            mma_chunk64(acc, cb, cb + HPLANE, aoff, boff);
            if (c + 1 < 8) CP_WAIT0();
            __syncthreads();
            buf ^= 1;
        }

        epi_ln_split(acc, bias, res, Cf, lnw, lnb, oh, rsum, rsq, m0, wm, wn, lane);
        __syncthreads();
    }
}

// ---------------------------------------------------------------------------
// Final FC on tensor path
// ---------------------------------------------------------------------------
__global__ void __launch_bounds__(256, 2) tgemm_fc(
    const __half* __restrict__ Ah, const __half* __restrict__ Bh,
    float* __restrict__ part)
{
    extern __shared__ char smraw[];
    uint32_t sb = smem_u32(smraw);
    const int lda = FCK;

    int tid = threadIdx.x, wid = tid >> 5, lane = tid & 31;
    int wm = wid >> 2, wn = wid & 3;
    int m0 = blockIdx.x * 128;
    int kbase = blockIdx.y * 1024;

    const uint32_t aoff = ((wm * 64 + (lane & 15)) * PAD2 + (lane >> 4) * 8) * 2;
    const uint32_t boff = ((wn * 32 + ((lane >> 4) << 3) + (lane & 7)) * PAD2
                          + ((lane >> 3) & 1) * 8) * 2;

    float acc[4][4][4];
#pragma unroll
    for (int mi = 0; mi < 4; ++mi)
#pragma unroll
        for (int ni = 0; ni < 4; ++ni)
#pragma unroll
            for (int e = 0; e < 4; ++e) acc[mi][ni][e] = 0.f;

    stage_async64(Ah + (size_t)m0 * lda + kbase, lda, sb,          tid);
    stage_async64(Bh + kbase,                    lda, sb + HPLANE, tid);
    CP_COMMIT();
    CP_WAIT0();
    __syncthreads();

    int buf = 0;
    for (int c = 0; c < 16; ++c) {
        if (c + 1 < 16) {
            uint32_t nb = sb + (buf ^ 1) * 2 * HPLANE;
            int ko = kbase + (c + 1) * 64;
            stage_async64(Ah + (size_t)m0 * lda + ko, lda, nb,          tid);
            stage_async64(Bh + ko,                    lda, nb + HPLANE, tid);
            CP_COMMIT();
        }
        uint32_t cb = sb + buf * 2 * HPLANE;
        mma_chunk64(acc, cb, cb + HPLANE, aoff, boff);
        if (c + 1 < 16) CP_WAIT0();
        __syncthreads();
        buf ^= 1;
    }

    float* Cp = part + (size_t)blockIdx.y * Bx * Dx;
    int gp = lane >> 2, t4 = lane & 3;
#pragma unroll
    for (int mi = 0; mi < 4; ++mi) {
        int mrow = m0 + wm * 64 + mi * 16 + gp;
#pragma unroll
        for (int ni = 0; ni < 4; ++ni) {
            int ncol = wn * 32 + ni * 8 + t4 * 2;
            *(float2*)(Cp + (size_t)mrow * Dx + ncol) =
                make_float2(acc[mi][ni][0], acc[mi][ni][1]);
            *(float2*)(Cp + (size_t)(mrow + 8) * Dx + ncol) =
                make_float2(acc[mi][ni][2], acc[mi][ni][3]);
        }
    }
}

__global__ void fcred_k(const float* __restrict__ part, const float* __restrict__ bias,
                        float* __restrict__ out) {
    int idx = blockIdx.x * 256 + threadIdx.x;
    if (idx >= Bx * Dx) return;
    float s = 0.f;
#pragma unroll
    for (int z = 0; z < FCZ; ++z) s += part[(size_t)z * Bx * Dx + idx];
    out[idx] = s + bias[idx & (Dx - 1)];
}

// ---------------------------------------------------------------------------
// Fused masked attention (fp32 math; fp16 output plane)
// ---------------------------------------------------------------------------
#define AKS 36
#define AVS 204
#define ATTN_SMEM_FLOATS (200*AKS + 32*AVS + 200 + 8*2*AVS)
#define ATTN_SMEM_BYTES  (ATTN_SMEM_FLOATS * 4)

__global__ void __launch_bounds__(256) attn_k(
    const float* __restrict__ Q, const float* __restrict__ Kx,
    const float* __restrict__ Vx, const int* __restrict__ seqs,
    __half* __restrict__ Oh)
{
    int h = blockIdx.x, b = blockIdx.y;
    extern __shared__ float sm[];
    float* Ks   = sm;
    float* Vt   = Ks + 200 * AKS;
    float* flag = Vt + 32 * AVS;
    float* ps   = flag + 200;

    int tid = threadIdx.x;
    size_t base = ((size_t)b * Lx) * Dx + h * DKx;

    for (int idx = tid; idx < 1600; idx += 256) {
        int l = idx >> 3, i = idx & 7;
        float4 v = *(const float4*)(Kx + base + (size_t)l * Dx + i * 4);
        *(float4*)(Ks + l * AKS + i * 4) = v;
    }
    for (int idx = tid; idx < 6400; idx += 256) {
        int l = idx >> 5, d = idx & 31;
        Vt[d * AVS + l] = Vx[base + (size_t)l * Dx + d];
    }
    for (int l = tid; l < 200; l += 256)
        flag[l] = (seqs[b * Lx + l] > 0) ? 1.f : 0.f;
    __syncthreads();

    int warp = tid >> 5, lane = tid & 31;
    float* psw = ps + warp * 2 * AVS;
    const float scale = 0.17677669529663687f;

    for (int qp = warp; qp < 100; qp += 8) {
        int q0 = qp, q1 = qp + 100;
        float4 qa[8], qb[8];
        const float4* q0p = (const float4*)(Q + base + (size_t)q0 * Dx);
        const float4* q1p = (const float4*)(Q + base + (size_t)q1 * Dx);
#pragma unroll
        for (int i = 0; i < 8; ++i) { qa[i] = q0p[i]; qb[i] = q1p[i]; }

        float s0[7], s1[7], mx0 = -1e30f, mx1 = -1e30f;
#pragma unroll
        for (int j = 0; j < 7; ++j) {
            int k = j * 32 + lane;
            const float* kr = Ks + k * AKS;
            float d0 = 0.f, d1 = 0.f;
#pragma unroll
            for (int i = 0; i < 8; ++i) {
                float4 kv = *(const float4*)(kr + i * 4);
                d0 = fmaf(qa[i].x, kv.x, d0); d0 = fmaf(qa[i].y, kv.y, d0);
                d0 = fmaf(qa[i].z, kv.z, d0); d0 = fmaf(qa[i].w, kv.w, d0);
                d1 = fmaf(qb[i].x, kv.x, d1); d1 = fmaf(qb[i].y, kv.y, d1);
                d1 = fmaf(qb[i].z, kv.z, d1); d1 = fmaf(qb[i].w, kv.w, d1);
            }
            bool valid = (k < 200);
            float fl = valid ? flag[k] : 0.f;
            float v0 = (fl != 0.f) ? d0 * scale : -1e9f;
            float v1 = (fl != 0.f) ? d1 * scale : -1e9f;
            s0[j] = valid ? v0 : -1e30f;
            s1[j] = valid ? v1 : -1e30f;
            mx0 = fmaxf(mx0, s0[j]);
            mx1 = fmaxf(mx1, s1[j]);
        }
#pragma unroll
        for (int o = 16; o; o >>= 1) {
            mx0 = fmaxf(mx0, __shfl_xor_sync(~0u, mx0, o));
            mx1 = fmaxf(mx1, __shfl_xor_sync(~0u, mx1, o));
        }

        float p0[7], p1[7], sum0 = 0.f, sum1 = 0.f;
#pragma unroll
        for (int j = 0; j < 7; ++j) {
            p0[j] = __expf(s0[j] - mx0); sum0 += p0[j];
            p1[j] = __expf(s1[j] - mx1); sum1 += p1[j];
        }
#pragma unroll
        for (int o = 16; o; o >>= 1) {
            sum0 += __shfl_xor_sync(~0u, sum0, o);
            sum1 += __shfl_xor_sync(~0u, sum1, o);
        }
        float inv0 = 1.f / sum0, inv1 = 1.f / sum1;

#pragma unroll
        for (int j = 0; j < 7; ++j) {
            int k = j * 32 + lane;
            if (k < 200) { psw[k] = p0[j]; psw[AVS + k] = p1[j]; }
        }
        __syncwarp();

        float a0 = 0.f, a1 = 0.f;
        const float* vr = Vt + lane * AVS;
#pragma unroll
        for (int kg = 0; kg < 50; ++kg) {
            float4 pv0 = *(const float4*)(psw + kg * 4);
            float4 pv1 = *(const float4*)(psw + AVS + kg * 4);
            float4 vv  = *(const float4*)(vr + kg * 4);
            a0 = fmaf(pv0.x, vv.x, a0); a0 = fmaf(pv0.y, vv.y, a0);
            a0 = fmaf(pv0.z, vv.z, a0); a0 = fmaf(pv0.w, vv.w, a0);
            a1 = fmaf(pv1.x, vv.x, a1); a1 = fmaf(pv1.y, vv.y, a1);
            a1 = fmaf(pv1.z, vv.z, a1); a1 = fmaf(pv1.w, vv.w, a1);
        }
        Oh[base + (size_t)q0 * Dx + lane] = __float2half_rn(a0 * inv0);
        Oh[base + (size_t)q1 * Dx + lane] = __float2half_rn(a1 * inv1);
        __syncwarp();
    }
}

// ---------------------------------------------------------------------------
// Host driver
// ---------------------------------------------------------------------------
extern "C" void kernel_launch(void* const* d_in, const int* in_sizes, int n_in,
                              void* d_out, int out_size) {
    (void)in_sizes; (void)n_in; (void)out_size;
    const int*   seqs = (const int*)  d_in[0];
    const float* tok  = (const float*)d_in[1];
    const float* pos  = (const float*)d_in[2];
    const float* Wq   = (const float*)d_in[3];
    const float* bq   = (const float*)d_in[4];
    const float* Wk   = (const float*)d_in[5];
    const float* bk   = (const float*)d_in[6];
    const float* Wv   = (const float*)d_in[7];
    const float* bv   = (const float*)d_in[8];
    const float* Wo   = (const float*)d_in[9];
    const float* bo   = (const float*)d_in[10];
    const float* ln1w = (const float*)d_in[11];
    const float* ln1b = (const float*)d_in[12];
    const float* ln2w = (const float*)d_in[13];
    const float* ln2b = (const float*)d_in[14];
    const float* W1   = (const float*)d_in[15];
    const float* b1   = (const float*)d_in[16];
    const float* W2   = (const float*)d_in[17];
    const float* b2   = (const float*)d_in[18];
    const float* fcW  = (const float*)d_in[19];
    const float* fcb  = (const float*)d_in[20];
    float* out = (float*)d_out;

    float *px, *pq, *pk, *pv, *pp;
    __half *pa, *po, *pf, *pw, *pfw;
    cudaGetSymbolAddress((void**)&px, g_x);
    cudaGetSymbolAddress((void**)&pq, g_q);
    cudaGetSymbolAddress((void**)&pk, g_k);
    cudaGetSymbolAddress((void**)&pv, g_v);
    cudaGetSymbolAddress((void**)&pp, g_fcp);
    cudaGetSymbolAddress((void**)&pa, g_a);
    cudaGetSymbolAddress((void**)&po, g_o);
    cudaGetSymbolAddress((void**)&pf, g_f);
    cudaGetSymbolAddress((void**)&pw, g_w);
    cudaGetSymbolAddress((void**)&pfw, g_fcw);

    cudaFuncSetAttribute(attn_k, cudaFuncAttributeMaxDynamicSharedMemorySize, ATTN_SMEM_BYTES);
    cudaFuncSetAttribute(tgemm<1>, cudaFuncAttributeMaxDynamicSharedMemorySize, TG_SMEM);
    cudaFuncSetAttribute(tgemm<2>, cudaFuncAttributeMaxDynamicSharedMemorySize, TG_SMEM_LN);
    cudaFuncSetAttribute(tgemm<5>, cudaFuncAttributeMaxDynamicSharedMemorySize, TG_SMEM);
    cudaFuncSetAttribute(tgemm_w2, cudaFuncAttributeMaxDynamicSharedMemorySize, W2_SMEM_LN);
    cudaFuncSetAttribute(tgemm_fc, cudaFuncAttributeMaxDynamicSharedMemorySize, FC_SMEM);

    wconv_all<<<(NLx * LW + 255) / 256, 256>>>(Wq, Wk, Wv, Wo, W1, W2, pw);
    wconv_fc<<<(Dx * FCK + 255) / 256, 256>>>(fcW, pfw);

    const dim3 gRow(NT / 8);
    const int  MT = NT / 128;  // 1600

    embed_k<<<gRow, 256>>>(seqs, tok, pos, px);
    ln_k<<<gRow, 256>>>(px, ln1w, ln1b, pa);   // layer 0 ln1 only

    for (int i = 0; i < NLx; ++i) {
        size_t wb = (size_t)i * LW;
        // --- attention block ---
        tgemm<5><<<dim3(3,296), 256, TG_SMEM>>>(pa, Dx, pw + wb,
                 bq + i*Dx, bk + i*Dx, bv + i*Dx, nullptr,
                 pq, pk, pv, nullptr, Dx, MT);
        attn_k<<<dim3(Hx, Bx), 256, ATTN_SMEM_BYTES>>>(pq, pk, pv, seqs, po);
        // Wo GEMM + residual + fused LN2 -> fp16 plane for W1
        tgemm<2><<<dim3(1,296), 256, TG_SMEM_LN>>>(po, Dx, pw + wb + 49152,
                 bo + i*Dx, ln2w + i*Dx, ln2b + i*Dx, px,
                 px, nullptr, nullptr, pa, Dx, MT);
        // --- FFN block ---
        tgemm<1><<<dim3(4,74), 256, TG_SMEM>>>(pa, Dx, pw + wb + 65536,
                 b1 + i*FFx, nullptr, nullptr, nullptr,
                 nullptr, nullptr, nullptr, pf, FFx, MT);
        // W2 GEMM + residual + fused LN1(next) or plain convert (last layer)
        const float* nlw = (i + 1 < NLx) ? (ln1w + (i + 1) * Dx) : nullptr;
        const float* nlb = (i + 1 < NLx) ? (ln1b + (i + 1) * Dx) : nullptr;
        tgemm_w2<<<dim3(1,296), 256, W2_SMEM_LN>>>(pf, pw + wb + 131072,
                 b2 + i*Dx, px, px, nlw, nlb, pa, MT);
    }

    // Final FC on tensor path (fp16 plane produced by last W2 epilogue)
    tgemm_fc<<<dim3(Bx / 128, FCZ), 256, FC_SMEM>>>(pa, pfw, pp);
    fcred_k<<<(Bx * Dx + 255) / 256, 256>>>(pp, fcb, out);
}